// round 1
// baseline (speedup 1.0000x reference)
#include <cuda_runtime.h>
#include <math.h>

#define H      2048
#define HH     1024
#define NB     4
#define S      4096
#define NROWS  (NB*S)          // 16384 rows per matrix
#define SCHUNK 128
#define NCHUNK (S/SCHUNK)      // 32
#define TILE_R 64
#define MAIN_THREADS 512

// ---------------- device scratch (no allocation allowed) ----------------
__device__ float g_partial[NB*NCHUNK*H];   // 1 MB, fully overwritten each call
__device__ float g_hid[NB*HH];
__device__ int   g_rank;

// ---------------- kernel 1: chunked column sums of keys over S ----------
__global__ void k_mean_partial(const float* __restrict__ keys) {
    int b = blockIdx.y, c = blockIdx.x;
    const float* base = keys + ((size_t)b * S + (size_t)c * SCHUNK) * H + threadIdx.x;
    float a0 = 0.f, a1 = 0.f;
#pragma unroll 4
    for (int s = 0; s < SCHUNK; s++) {
        a0 += base[(size_t)s * H];
        a1 += base[(size_t)s * H + 1024];
    }
    g_partial[(b * NCHUNK + c) * H + threadIdx.x]        = a0;
    g_partial[(b * NCHUNK + c) * H + threadIdx.x + 1024] = a1;
}

// ---------------- kernel 2: hidden layer h = relu(x_mean @ w1 + b1) -----
__global__ void k_mlp1(const float* __restrict__ w1, const float* __restrict__ b1) {
    __shared__ float sx[H];
    int b = blockIdx.y;
    for (int h = threadIdx.x; h < H; h += blockDim.x) {
        float s = 0.f;
#pragma unroll
        for (int c = 0; c < NCHUNK; c++) s += g_partial[(b * NCHUNK + c) * H + h];
        sx[h] = s * (1.0f / (float)S);
    }
    __syncthreads();
    int j = blockIdx.x * blockDim.x + threadIdx.x;   // j in [0, HH)
    float acc = b1[j];
#pragma unroll 8
    for (int h = 0; h < H; h++) acc = fmaf(sx[h], w1[(size_t)h * HH + j], acc);
    g_hid[b * HH + j] = fmaxf(acc, 0.f);
}

// ---------------- kernel 3: output layer + sigmoid + rank select --------
__global__ void k_select(const float* __restrict__ w2, const float* __restrict__ b2) {
    __shared__ float red[128];
    __shared__ float s_avg;
    int t = threadIdx.x;
    if (t == 0) s_avg = 0.f;
    __syncthreads();
    for (int b = 0; b < NB; b++) {
        float acc = 0.f;
        for (int j = t; j < HH; j += 128) acc += g_hid[b * HH + j] * w2[j];
        red[t] = acc;
        __syncthreads();
        for (int o = 64; o > 0; o >>= 1) {
            if (t < o) red[t] += red[t + o];
            __syncthreads();
        }
        if (t == 0) {
            float v = red[0] + b2[0];
            s_avg += 1.f / (1.f + expf(-v));
        }
        __syncthreads();
    }
    if (t == 0) {
        float avg = s_avg * 0.25f;
        g_rank = (int)(avg >= 0.3f) + (int)(avg >= 0.7f);
    }
}

// ---------------- main fused kernel: out = x + (x @ A) @ B --------------
// One instantiation per rank; non-selected ranks early-exit.
template <int R, int IDX>
__global__ void __launch_bounds__(MAIN_THREADS, 1)
k_main(const float* __restrict__ keys, const float* __restrict__ values,
       const float* __restrict__ kA, const float* __restrict__ kB,
       const float* __restrict__ vA, const float* __restrict__ vB,
       float* __restrict__ out) {
    if (g_rank != IDX) return;

    extern __shared__ float smem[];
    float* s_w = smem;             // R*H floats (kA transposed, then kB)
    float* s_P = smem + R * H;     // TILE_R*R floats

    int row0 = blockIdx.x * TILE_R;              // global row over both matrices
    const float* src; const float* A; const float* Bw; float* dst;
    if (row0 < NROWS) { src = keys;   A = kA; Bw = kB; dst = out; }
    else { row0 -= NROWS; src = values; A = vA; Bw = vB; dst = out + (size_t)NROWS * H; }

    int tid = threadIdx.x;

    // Load A [H][R] into smem transposed: s_w[j*H + h] = A[h*R + j]
    for (int idx = tid; idx < H * R; idx += MAIN_THREADS) {
        int h = idx / R, j = idx - h * R;
        s_w[j * H + h] = A[idx];
    }
    __syncthreads();

    // ---- Phase 1: P[row][j] = row . A[:,j]; warp handles 4 rows --------
    {
        int w = tid >> 5, l = tid & 31;          // 16 warps * 4 rows = 64 rows
        float acc[4][R];
#pragma unroll
        for (int i = 0; i < 4; i++)
#pragma unroll
            for (int j = 0; j < R; j++) acc[i][j] = 0.f;

        const float4* rp0 = (const float4*)(src + (size_t)(row0 + w * 4 + 0) * H);
        const float4* rp1 = (const float4*)(src + (size_t)(row0 + w * 4 + 1) * H);
        const float4* rp2 = (const float4*)(src + (size_t)(row0 + w * 4 + 2) * H);
        const float4* rp3 = (const float4*)(src + (size_t)(row0 + w * 4 + 3) * H);

#pragma unroll 2
        for (int h4 = l; h4 < H / 4; h4 += 32) {
            float4 k0 = rp0[h4], k1 = rp1[h4], k2 = rp2[h4], k3 = rp3[h4];
#pragma unroll
            for (int j = 0; j < R; j++) {
                float4 a = *(const float4*)(s_w + j * H + h4 * 4);
                acc[0][j] += k0.x * a.x + k0.y * a.y + k0.z * a.z + k0.w * a.w;
                acc[1][j] += k1.x * a.x + k1.y * a.y + k1.z * a.z + k1.w * a.w;
                acc[2][j] += k2.x * a.x + k2.y * a.y + k2.z * a.z + k2.w * a.w;
                acc[3][j] += k3.x * a.x + k3.y * a.y + k3.z * a.z + k3.w * a.w;
            }
        }
#pragma unroll
        for (int i = 0; i < 4; i++)
#pragma unroll
            for (int j = 0; j < R; j++) {
                float v = acc[i][j];
#pragma unroll
                for (int o = 16; o > 0; o >>= 1) v += __shfl_xor_sync(0xffffffffu, v, o);
                if (l == 0) s_P[(w * 4 + i) * R + j] = v;
            }
    }
    __syncthreads();

    // Overwrite s_w with B [R][H] (same layout, straight copy)
    for (int idx = tid; idx < R * H; idx += MAIN_THREADS) s_w[idx] = Bw[idx];
    __syncthreads();

    // ---- Phase 2: out[row][h] = src[row][h] + sum_j P[row][j]*B[j][h] ---
    // Thread tid owns float4-column tid (H/4 = 512 = MAIN_THREADS). 4-row blocking.
#pragma unroll 1
    for (int g = 0; g < TILE_R; g += 4) {
        float p[4][R];
#pragma unroll
        for (int i = 0; i < 4; i++)
#pragma unroll
            for (int j = 0; j < R; j++) p[i][j] = s_P[(g + i) * R + j];

        float4 o0 = ((const float4*)(src + (size_t)(row0 + g + 0) * H))[tid];
        float4 o1 = ((const float4*)(src + (size_t)(row0 + g + 1) * H))[tid];
        float4 o2 = ((const float4*)(src + (size_t)(row0 + g + 2) * H))[tid];
        float4 o3 = ((const float4*)(src + (size_t)(row0 + g + 3) * H))[tid];

#pragma unroll
        for (int j = 0; j < R; j++) {
            float4 bv = *(const float4*)(s_w + j * H + tid * 4);
            o0.x += p[0][j] * bv.x; o0.y += p[0][j] * bv.y; o0.z += p[0][j] * bv.z; o0.w += p[0][j] * bv.w;
            o1.x += p[1][j] * bv.x; o1.y += p[1][j] * bv.y; o1.z += p[1][j] * bv.z; o1.w += p[1][j] * bv.w;
            o2.x += p[2][j] * bv.x; o2.y += p[2][j] * bv.y; o2.z += p[2][j] * bv.z; o2.w += p[2][j] * bv.w;
            o3.x += p[3][j] * bv.x; o3.y += p[3][j] * bv.y; o3.z += p[3][j] * bv.z; o3.w += p[3][j] * bv.w;
        }

        ((float4*)(dst + (size_t)(row0 + g + 0) * H))[tid] = o0;
        ((float4*)(dst + (size_t)(row0 + g + 1) * H))[tid] = o1;
        ((float4*)(dst + (size_t)(row0 + g + 2) * H))[tid] = o2;
        ((float4*)(dst + (size_t)(row0 + g + 3) * H))[tid] = o3;
    }
}

// ---------------- launch -------------------------------------------------
extern "C" void kernel_launch(void* const* d_in, const int* in_sizes, int n_in,
                              void* d_out, int out_size) {
    const float* keys   = (const float*)d_in[0];
    const float* values = (const float*)d_in[1];
    const float* w1     = (const float*)d_in[2];
    const float* b1     = (const float*)d_in[3];
    const float* w2     = (const float*)d_in[4];
    const float* b2     = (const float*)d_in[5];
    const float* kA0 = (const float*)d_in[6];  const float* kB0 = (const float*)d_in[7];
    const float* vA0 = (const float*)d_in[8];  const float* vB0 = (const float*)d_in[9];
    const float* kA1 = (const float*)d_in[10]; const float* kB1 = (const float*)d_in[11];
    const float* vA1 = (const float*)d_in[12]; const float* vB1 = (const float*)d_in[13];
    const float* kA2 = (const float*)d_in[14]; const float* kB2 = (const float*)d_in[15];
    const float* vA2 = (const float*)d_in[16]; const float* vB2 = (const float*)d_in[17];
    float* out = (float*)d_out;

    // smem sizes per instantiation
    const int smem4  = (4  * H + TILE_R * 4 ) * (int)sizeof(float);   //  33,792
    const int smem8  = (8  * H + TILE_R * 8 ) * (int)sizeof(float);   //  67,584
    const int smem16 = (16 * H + TILE_R * 16) * (int)sizeof(float);   // 135,168

    cudaFuncSetAttribute(k_main<4, 0>,  cudaFuncAttributeMaxDynamicSharedMemorySize, smem4);
    cudaFuncSetAttribute(k_main<8, 1>,  cudaFuncAttributeMaxDynamicSharedMemorySize, smem8);
    cudaFuncSetAttribute(k_main<16, 2>, cudaFuncAttributeMaxDynamicSharedMemorySize, smem16);

    k_mean_partial<<<dim3(NCHUNK, NB), 1024>>>(keys);
    k_mlp1<<<dim3(HH / 128, NB), 128>>>(w1, b1);
    k_select<<<1, 128>>>(w2, b2);

    const int grid = (2 * NROWS) / TILE_R;   // 512 CTAs
    k_main<4, 0><<<grid, MAIN_THREADS, smem4 >>>(keys, values, kA0, kB0, vA0, vB0, out);
    k_main<8, 1><<<grid, MAIN_THREADS, smem8 >>>(keys, values, kA1, kB1, vA1, vB1, out);
    k_main<16, 2><<<grid, MAIN_THREADS, smem16>>>(keys, values, kA2, kB2, vA2, vB2, out);
}

// round 2
// speedup vs baseline: 1.6579x; 1.6579x over previous
#include <cuda_runtime.h>
#include <math.h>

#define H      2048
#define HH     1024
#define NB     4
#define S      4096
#define NROWS  (NB*S)          // 16384 rows per matrix
#define SCHUNK 64
#define NCHUNK (S/SCHUNK)      // 64
#define TILE_R 32
#define MAIN_THREADS 512

typedef unsigned long long ull;

// ---------------- packed f32x2 helpers ----------------------------------
__device__ __forceinline__ ull pack2(float lo, float hi) {
    ull r; asm("mov.b64 %0, {%1, %2};" : "=l"(r) : "f"(lo), "f"(hi)); return r;
}
__device__ __forceinline__ ull fma2(ull a, ull b, ull c) {
    ull d; asm("fma.rn.f32x2 %0, %1, %2, %3;" : "=l"(d) : "l"(a), "l"(b), "l"(c)); return d;
}
__device__ __forceinline__ float pairsum(ull a) {
    float lo, hi; asm("mov.b64 {%0, %1}, %2;" : "=f"(lo), "=f"(hi) : "l"(a)); return lo + hi;
}

// ---------------- device scratch (no allocation allowed) ----------------
__device__ float g_partial[NB*NCHUNK*H];   // 2 MB, fully overwritten each call
__device__ float g_h1p[NB*8*HH];           // partial hidden sums (8 h-chunks)
__device__ int   g_rank;

// ---------------- kernel 1: chunked column sums of keys over S ----------
__global__ void k_mean_partial(const float* __restrict__ keys) {
    int b = blockIdx.y, c = blockIdx.x;
    const float4* base = (const float4*)(keys + ((size_t)b * S + (size_t)c * SCHUNK) * H);
    int t = threadIdx.x;                    // 512 threads cover H/4 float4 cols
    float4 a = make_float4(0.f, 0.f, 0.f, 0.f);
#pragma unroll 4
    for (int s = 0; s < SCHUNK; s++) {
        float4 v = base[(size_t)s * (H / 4) + t];
        a.x += v.x; a.y += v.y; a.z += v.z; a.w += v.w;
    }
    ((float4*)(g_partial + ((size_t)b * NCHUNK + c) * H))[t] = a;
}

// ---------------- kernel 2: partial hidden GEMV --------------------------
// grid (4 jb, 8 hc, NB b), 256 threads. h1p[b][hc][j] = sum over 256 h of
// x_mean[b][h] * w1[h][j].
__global__ void k_gemv1(const float* __restrict__ w1) {
    __shared__ float sx[256];
    int jb = blockIdx.x, hc = blockIdx.y, b = blockIdx.z;
    int t = threadIdx.x;
    // finalize column mean for this h-chunk
    {
        int h = hc * 256 + t;
        float s0 = 0.f, s1 = 0.f, s2 = 0.f, s3 = 0.f;
#pragma unroll
        for (int c = 0; c < NCHUNK; c += 4) {
            s0 += g_partial[((size_t)b * NCHUNK + c + 0) * H + h];
            s1 += g_partial[((size_t)b * NCHUNK + c + 1) * H + h];
            s2 += g_partial[((size_t)b * NCHUNK + c + 2) * H + h];
            s3 += g_partial[((size_t)b * NCHUNK + c + 3) * H + h];
        }
        sx[t] = (s0 + s1 + s2 + s3) * (1.0f / (float)S);
    }
    __syncthreads();
    int j = jb * 256 + t;
    const float* wp = w1 + (size_t)(hc * 256) * HH + j;
    float a0 = 0.f, a1 = 0.f, a2 = 0.f, a3 = 0.f;
#pragma unroll 8
    for (int hh = 0; hh < 256; hh += 4) {
        a0 = fmaf(sx[hh + 0], wp[(size_t)(hh + 0) * HH], a0);
        a1 = fmaf(sx[hh + 1], wp[(size_t)(hh + 1) * HH], a1);
        a2 = fmaf(sx[hh + 2], wp[(size_t)(hh + 2) * HH], a2);
        a3 = fmaf(sx[hh + 3], wp[(size_t)(hh + 3) * HH], a3);
    }
    g_h1p[((size_t)b * 8 + hc) * HH + j] = (a0 + a1) + (a2 + a3);
}

// ---------------- kernel 3: relu + layer2 + sigmoid + rank select -------
__global__ void k_select(const float* __restrict__ b1, const float* __restrict__ w2,
                         const float* __restrict__ b2) {
    __shared__ float red[256];
    __shared__ float s_avg;
    int t = threadIdx.x;
    if (t == 0) s_avg = 0.f;
    __syncthreads();
    for (int b = 0; b < NB; b++) {
        float acc = 0.f;
#pragma unroll
        for (int k = 0; k < 4; k++) {
            int j = t + k * 256;
            float hv = b1[j];
#pragma unroll
            for (int hc = 0; hc < 8; hc++) hv += g_h1p[((size_t)b * 8 + hc) * HH + j];
            acc += fmaxf(hv, 0.f) * w2[j];
        }
        red[t] = acc;
        __syncthreads();
        for (int o = 128; o > 0; o >>= 1) {
            if (t < o) red[t] += red[t + o];
            __syncthreads();
        }
        if (t == 0) {
            float v = red[0] + b2[0];
            s_avg += 1.f / (1.f + expf(-v));
        }
        __syncthreads();
    }
    if (t == 0) {
        float avg = s_avg * 0.25f;
        g_rank = (int)(avg >= 0.3f) + (int)(avg >= 0.7f);
    }
}

// ---------------- main body: out = x + (x @ A) @ B ----------------------
template <int R>
__device__ __forceinline__ void main_body(
    const float* __restrict__ keys, const float* __restrict__ values,
    const float* __restrict__ kA, const float* __restrict__ kB,
    const float* __restrict__ vA, const float* __restrict__ vB,
    float* __restrict__ out, float* smem) {

    constexpr bool RESIDENT = (R <= 8);
    float* s_A  = smem;                                 // R*H (A transposed)
    float* s_B  = RESIDENT ? (smem + R * H) : smem;     // R*H
    float* s_P2 = smem + (RESIDENT ? 2 * R * H : R * H);// TILE_R*R*2 (dup pairs)

    int row0 = blockIdx.x * TILE_R;
    const float* src; const float* A; const float* Bw; float* dst;
    if (row0 < NROWS) { src = keys;   A = kA; Bw = kB; dst = out; }
    else { row0 -= NROWS; src = values; A = vA; Bw = vB; dst = out + (size_t)NROWS * H; }

    int tid = threadIdx.x;

    // Load A [H][R] transposed: s_A[j*H + h] = A[h*R + j]
    for (int idx = tid; idx < H * R; idx += MAIN_THREADS) {
        int h = idx >> __builtin_ctz(R) ? 0 : 0, j;     // (placeholder, replaced below)
        (void)h; (void)j;
    }
    // (the loop above is rewritten cleanly here; R is a power of two)
    {
        constexpr int SH = (R == 4) ? 2 : (R == 8) ? 3 : 4;
        for (int idx = tid; idx < H * R; idx += MAIN_THREADS) {
            int h = idx >> SH, j = idx & (R - 1);
            s_A[j * H + h] = A[idx];
        }
        if (RESIDENT)
            for (int idx = tid; idx < R * H; idx += MAIN_THREADS) s_B[idx] = Bw[idx];
    }
    __syncthreads();

    // ---- Phase 1: P[row][j] = row . A[:,j]; 16 warps x 2 rows ----------
    {
        int w = tid >> 5, l = tid & 31;
        ull acc[2][R];
#pragma unroll
        for (int i = 0; i < 2; i++)
#pragma unroll
            for (int j = 0; j < R; j++) acc[i][j] = 0ull;

        const ulonglong2* rp0 = (const ulonglong2*)(src + (size_t)(row0 + w * 2 + 0) * H);
        const ulonglong2* rp1 = (const ulonglong2*)(src + (size_t)(row0 + w * 2 + 1) * H);

#pragma unroll 2
        for (int h4 = l; h4 < H / 4; h4 += 32) {
            ulonglong2 k0 = rp0[h4], k1 = rp1[h4];
#pragma unroll
            for (int j = 0; j < R; j++) {
                ulonglong2 aq = *(const ulonglong2*)(s_A + j * H + h4 * 4);
                acc[0][j] = fma2(k0.x, aq.x, acc[0][j]);
                acc[0][j] = fma2(k0.y, aq.y, acc[0][j]);
                acc[1][j] = fma2(k1.x, aq.x, acc[1][j]);
                acc[1][j] = fma2(k1.y, aq.y, acc[1][j]);
            }
        }
#pragma unroll
        for (int i = 0; i < 2; i++)
#pragma unroll
            for (int j = 0; j < R; j++) {
                float v = pairsum(acc[i][j]);
#pragma unroll
                for (int o = 16; o > 0; o >>= 1) v += __shfl_xor_sync(0xffffffffu, v, o);
                if (l == 0) *(ull*)(s_P2 + ((w * 2 + i) * R + j) * 2) = pack2(v, v);
            }
    }
    __syncthreads();

    if (!RESIDENT) {   // overwrite A buffer with B for the second phase
        for (int idx = tid; idx < R * H; idx += MAIN_THREADS) s_B[idx] = Bw[idx];
        __syncthreads();
    }

    // ---- Phase 2: out[row][h] = src[row][h] + sum_j P[row][j]*B[j][h] ---
    // 512 threads each own one float4 column. 4-row register blocking.
#pragma unroll 1
    for (int g = 0; g < TILE_R; g += 4) {
        ulonglong2 o0 = ((const ulonglong2*)(src + (size_t)(row0 + g + 0) * H))[tid];
        ulonglong2 o1 = ((const ulonglong2*)(src + (size_t)(row0 + g + 1) * H))[tid];
        ulonglong2 o2 = ((const ulonglong2*)(src + (size_t)(row0 + g + 2) * H))[tid];
        ulonglong2 o3 = ((const ulonglong2*)(src + (size_t)(row0 + g + 3) * H))[tid];

#pragma unroll
        for (int j = 0; j < R; j++) {
            ulonglong2 bq = *(const ulonglong2*)(s_B + j * H + tid * 4);
            ull p0 = *(const ull*)(s_P2 + ((g + 0) * R + j) * 2);
            ull p1 = *(const ull*)(s_P2 + ((g + 1) * R + j) * 2);
            ull p2 = *(const ull*)(s_P2 + ((g + 2) * R + j) * 2);
            ull p3 = *(const ull*)(s_P2 + ((g + 3) * R + j) * 2);
            o0.x = fma2(bq.x, p0, o0.x); o0.y = fma2(bq.y, p0, o0.y);
            o1.x = fma2(bq.x, p1, o1.x); o1.y = fma2(bq.y, p1, o1.y);
            o2.x = fma2(bq.x, p2, o2.x); o2.y = fma2(bq.y, p2, o2.y);
            o3.x = fma2(bq.x, p3, o3.x); o3.y = fma2(bq.y, p3, o3.y);
        }

        ((ulonglong2*)(dst + (size_t)(row0 + g + 0) * H))[tid] = o0;
        ((ulonglong2*)(dst + (size_t)(row0 + g + 1) * H))[tid] = o1;
        ((ulonglong2*)(dst + (size_t)(row0 + g + 2) * H))[tid] = o2;
        ((ulonglong2*)(dst + (size_t)(row0 + g + 3) * H))[tid] = o3;
    }
}

// single kernel, uniform branch on g_rank — no dead launches
__global__ void __launch_bounds__(MAIN_THREADS, 1)
k_main_all(const float* __restrict__ keys, const float* __restrict__ values,
           const float* __restrict__ kA0, const float* __restrict__ kB0,
           const float* __restrict__ vA0, const float* __restrict__ vB0,
           const float* __restrict__ kA1, const float* __restrict__ kB1,
           const float* __restrict__ vA1, const float* __restrict__ vB1,
           const float* __restrict__ kA2, const float* __restrict__ kB2,
           const float* __restrict__ vA2, const float* __restrict__ vB2,
           float* __restrict__ out) {
    extern __shared__ float smem[];
    int r = g_rank;
    if (r == 0)      main_body<4>(keys, values, kA0, kB0, vA0, vB0, out, smem);
    else if (r == 1) main_body<8>(keys, values, kA1, kB1, vA1, vB1, out, smem);
    else             main_body<16>(keys, values, kA2, kB2, vA2, vB2, out, smem);
}

// ---------------- launch -------------------------------------------------
extern "C" void kernel_launch(void* const* d_in, const int* in_sizes, int n_in,
                              void* d_out, int out_size) {
    const float* keys   = (const float*)d_in[0];
    const float* values = (const float*)d_in[1];
    const float* w1     = (const float*)d_in[2];
    const float* b1     = (const float*)d_in[3];
    const float* w2     = (const float*)d_in[4];
    const float* b2     = (const float*)d_in[5];
    const float* kA0 = (const float*)d_in[6];  const float* kB0 = (const float*)d_in[7];
    const float* vA0 = (const float*)d_in[8];  const float* vB0 = (const float*)d_in[9];
    const float* kA1 = (const float*)d_in[10]; const float* kB1 = (const float*)d_in[11];
    const float* vA1 = (const float*)d_in[12]; const float* vB1 = (const float*)d_in[13];
    const float* kA2 = (const float*)d_in[14]; const float* kB2 = (const float*)d_in[15];
    const float* vA2 = (const float*)d_in[16]; const float* vB2 = (const float*)d_in[17];
    float* out = (float*)d_out;

    // max over branches: R=8 resident = (2*8*H + 32*8*2) floats = 133,120 B
    //                    R=16 two-phase = (16*H + 32*16*2) floats = 135,168 B
    const int smem_bytes = (16 * H + TILE_R * 16 * 2) * (int)sizeof(float);
    cudaFuncSetAttribute(k_main_all, cudaFuncAttributeMaxDynamicSharedMemorySize, smem_bytes);

    k_mean_partial<<<dim3(NCHUNK, NB), MAIN_THREADS>>>(keys);
    k_gemv1<<<dim3(4, 8, NB), 256>>>(w1);
    k_select<<<1, 256>>>(b1, w2, b2);

    const int grid = (2 * NROWS) / TILE_R;   // 1024 CTAs
    k_main_all<<<grid, MAIN_THREADS, smem_bytes>>>(
        keys, values,
        kA0, kB0, vA0, vB0,
        kA1, kB1, vA1, vB1,
        kA2, kB2, vA2, vB2,
        out);
}